// round 1
// baseline (speedup 1.0000x reference)
#include <cuda_runtime.h>
#include <math.h>

#define T_    4
#define C_    64
#define HH    96
#define WW    96
#define HW    9216
#define CI    16
#define PS    7
#define WS    21
#define NQX   24
#define NQ    576
#define NC    441
#define KSEL  100
#define SCALE 10.0f
#define RGN   27
#define RGN2  729
#define NT    256

// scratch (no allocations allowed in kernel_launch)
__device__ float g_b1[T_*CI*HW];
__device__ float g_b2[T_*CI*HW];
__device__ float g_b3[T_*CI*HW];
__device__ float g_acc[T_*CI*HW];
__device__ float g_Z[HW];

__device__ __forceinline__ int clipi(int v){ return min(max(v,0),95); }

// ---------------------------------------------------------------- zero
__global__ void k_zero(){
    int i = blockIdx.x*NT + threadIdx.x;
    if (i < T_*CI*HW) g_acc[i] = 0.f;
    if (i < HW)       g_Z[i]   = 0.f;
}

// ---------------------------------------------------------------- Z counts (t-independent)
__global__ void k_zcount(){
    int q  = blockIdx.x;
    int a  = threadIdx.x / PS, b = threadIdx.x % PS;
    int qi = (q / NQX)*4, qj = (q % NQX)*4;
    atomicAdd(&g_Z[min(qi+a,95)*WW + min(qj+b,95)], 1.0f);
}

// ---------------------------------------------------------------- fused 3x conv1x1
__global__ void k_proj(const float* __restrict__ vid,
                       const float* __restrict__ gw, const float* __restrict__ gb,
                       const float* __restrict__ tw, const float* __restrict__ tb,
                       const float* __restrict__ pw, const float* __restrict__ pb){
    __shared__ float sw[3*CI*C_ + 3*CI];
    for (int i=threadIdx.x; i<CI*C_; i+=NT){
        sw[i]          = gw[i];
        sw[CI*C_+i]    = tw[i];
        sw[2*CI*C_+i]  = pw[i];
    }
    if (threadIdx.x < CI){
        sw[3*CI*C_         + threadIdx.x] = gb[threadIdx.x];
        sw[3*CI*C_ +   CI  + threadIdx.x] = tb[threadIdx.x];
        sw[3*CI*C_ + 2*CI  + threadIdx.x] = pb[threadIdx.x];
    }
    __syncthreads();

    int gid = blockIdx.x*NT + threadIdx.x;   // [0, T*HW)
    int t = gid / HW, pix = gid % HW;

    float a1[CI], a2[CI], a3[CI];
    #pragma unroll
    for (int o=0;o<CI;o++){
        a1[o] = sw[3*CI*C_ + o];
        a2[o] = sw[3*CI*C_ + CI + o];
        a3[o] = sw[3*CI*C_ + 2*CI + o];
    }
    const float* vp = vid + (size_t)t*C_*HW + pix;
    for (int c=0;c<C_;c++){
        float v = vp[c*HW];
        #pragma unroll
        for (int o=0;o<CI;o++){
            a1[o] += v*sw[o*C_+c];
            a2[o] += v*sw[CI*C_ + o*C_+c];
            a3[o] += v*sw[2*CI*C_ + o*C_+c];
        }
    }
    float* o1 = g_b1 + (size_t)t*CI*HW + pix;
    float* o2 = g_b2 + (size_t)t*CI*HW + pix;
    float* o3 = g_b3 + (size_t)t*CI*HW + pix;
    #pragma unroll
    for (int o=0;o<CI;o++){ o1[o*HW]=a1[o]; o2[o*HW]=a2[o]; o3[o*HW]=a3[o]; }
}

// ---------------------------------------------------------------- main: scores + topk + softmax + aggregate + scatter
__global__ __launch_bounds__(NT) void k_score(){
    extern __shared__ float sm[];
    float* s_b1 = sm;                       // 784
    float* s_rg = sm + CI*49;               // 11664  (b3 region, later reused for b2)
    float* s_sc = s_rg + CI*RGN2;           // 512
    int*   s_id = (int*)(s_sc + 512);       // 512
    float* s_w  = (float*)(s_id + 512);     // 128

    int blk = blockIdx.x;
    int t = blk / NQ, q = blk % NQ;
    int qi = (q / NQX)*4, qj = (q % NQX)*4;
    int tid = threadIdx.x;

    int rmin = max(qi-10, 0), cmin = max(qj-10, 0);
    int rlim = 95 - rmin,     clim = 95 - cmin;

    // ---- load b3 region (absolute coords rmin..rmin+26, clipped) + b1 query patch
    const float* b3t = g_b3 + (size_t)t*CI*HW;
    for (int i=tid; i<CI*RGN2; i+=NT){
        int ci = i / RGN2, rem = i % RGN2;
        int rr = rem / RGN, cc = rem % RGN;
        s_rg[i] = b3t[ci*HW + min(rmin+rr,95)*WW + min(cmin+cc,95)];
    }
    const float* b1t = g_b1 + (size_t)t*CI*HW;
    for (int i=tid; i<CI*49; i+=NT){
        int ci = i/49, rem = i%49, a = rem/7, b = rem%7;
        s_b1[i] = b1t[ci*HW + min(qi+a,95)*WW + min(qj+b,95)];
    }
    __syncthreads();

    // ---- 441 correlation scores (double-clip semantics of the reference)
    for (int c=tid; c<512; c+=NT){
        float acc = -3.402823466e38f;
        if (c < NC){
            int di = c/WS, dj = c%WS;
            int cand_i = clipi(qi + di - 10);
            int cand_j = clipi(qj + dj - 10);
            int br = cand_i - rmin, bc = cand_j - cmin;
            int offr[PS], offc[PS];
            #pragma unroll
            for (int a=0;a<PS;a++){
                offr[a] = min(br+a, rlim)*RGN;
                offc[a] = min(bc+a, clim);
            }
            acc = 0.f;
            for (int ci=0; ci<CI; ci++){
                const float* bp = s_b1 + ci*49;
                const float* rp = s_rg + ci*RGN2;
                #pragma unroll
                for (int a=0;a<PS;a++){
                    const float* rpa = rp + offr[a];
                    #pragma unroll
                    for (int b=0;b<PS;b++)
                        acc += bp[a*7+b]*rpa[offc[b]];
                }
            }
        }
        s_sc[c] = acc;
        s_id[c] = c;
    }
    __syncthreads();

    // ---- bitonic sort 512 descending (256 threads, 1 pair/thread/step)
    for (int k=2; k<=512; k<<=1){
        for (int j=k>>1; j>0; j>>=1){
            int lo = tid & (j-1);
            int i0 = ((tid & ~(j-1))<<1) | lo;
            int i1 = i0 | j;
            bool desc = (i0 & k) == 0;
            float k0 = s_sc[i0], k1 = s_sc[i1];
            if ((k0 < k1) == desc){
                s_sc[i0]=k1; s_sc[i1]=k0;
                int tt=s_id[i0]; s_id[i0]=s_id[i1]; s_id[i1]=tt;
            }
            __syncthreads();
        }
    }

    // ---- softmax over top-100 (max-subtracted, as jax.nn.softmax)
    float maxv = s_sc[0];
    if (tid < KSEL) s_w[tid] = expf((s_sc[tid]-maxv)*SCALE);
    __syncthreads();
    if (tid == 0){
        float s = 0.f;
        for (int k=0;k<KSEL;k++) s += s_w[k];
        s_w[KSEL] = 1.f/s;
    }
    __syncthreads();
    if (tid < KSEL){
        s_w[tid] *= s_w[KSEL];
        int c = s_id[tid];
        int cand_i = clipi(qi + c/WS - 10);
        int cand_j = clipi(qj + c%WS - 10);
        s_id[tid] = (cand_i<<8) | cand_j;   // pack clipped candidate center
    }
    __syncthreads();

    // ---- reload region with b2 (same geometry)
    const float* b2t = g_b2 + (size_t)t*CI*HW;
    for (int i=tid; i<CI*RGN2; i+=NT){
        int ci = i / RGN2, rem = i % RGN2;
        int rr = rem / RGN, cc = rem % RGN;
        s_rg[i] = b2t[ci*HW + min(rmin+rr,95)*WW + min(cmin+cc,95)];
    }
    __syncthreads();

    // ---- zi = sum_k w_k * b2patch(pos_k); dims d = tid + 256*r
    float accz[4] = {0.f,0.f,0.f,0.f};
    int cia[4], aa[4], bb[4];
    #pragma unroll
    for (int r=0;r<4;r++){
        int d = tid + 256*r;
        if (d < CI*49){ cia[r]=d/49; int rem=d%49; aa[r]=rem/7; bb[r]=rem%7; }
        else { cia[r]=0; aa[r]=0; bb[r]=0; }
    }
    for (int k=0;k<KSEL;k++){
        float w  = s_w[k];
        int pk   = s_id[k];
        int ci_k = pk>>8, cj_k = pk & 255;
        #pragma unroll
        for (int r=0;r<4;r++){
            int d = tid + 256*r;
            if (d < CI*49){
                int row = min(ci_k + aa[r],95) - rmin;
                int col = min(cj_k + bb[r],95) - cmin;
                accz[r] += w * s_rg[cia[r]*RGN2 + row*RGN + col];
            }
        }
    }
    // ---- scatter-add into acc (query-clipped target pixels)
    #pragma unroll
    for (int r=0;r<4;r++){
        int d = tid + 256*r;
        if (d < CI*49){
            int pix = min(qi+aa[r],95)*WW + min(qj+bb[r],95);
            atomicAdd(&g_acc[(t*CI + cia[r])*HW + pix], accz[r]);
        }
    }
}

// ---------------------------------------------------------------- y = acc/Z ; out = vid + conv1x1(y)
__global__ void k_final(const float* __restrict__ vid, const float* __restrict__ Ww,
                        const float* __restrict__ Wb, float* __restrict__ out){
    __shared__ float sw[C_*CI + C_];
    for (int i=threadIdx.x; i<C_*CI; i+=NT) sw[i] = Ww[i];
    if (threadIdx.x < C_) sw[C_*CI+threadIdx.x] = Wb[threadIdx.x];
    __syncthreads();

    int gid = blockIdx.x*NT + threadIdx.x;
    int t = gid / HW, pix = gid % HW;

    float inv = 1.f / g_Z[pix];
    float y[CI];
    #pragma unroll
    for (int ci=0;ci<CI;ci++) y[ci] = g_acc[(t*CI+ci)*HW + pix]*inv;

    const float* vp = vid + (size_t)t*C_*HW + pix;
    float*       op = out + (size_t)t*C_*HW + pix;
    for (int co=0;co<C_;co++){
        float s = sw[C_*CI+co];
        #pragma unroll
        for (int ci=0;ci<CI;ci++) s += sw[co*CI+ci]*y[ci];
        op[co*HW] = vp[co*HW] + s;
    }
}

// ---------------------------------------------------------------- launch
extern "C" void kernel_launch(void* const* d_in, const int* in_sizes, int n_in,
                              void* d_out, int out_size){
    const float* vid  = (const float*)d_in[0];
    const float* g_w  = (const float*)d_in[1];
    const float* g_b  = (const float*)d_in[2];
    const float* th_w = (const float*)d_in[3];
    const float* th_b = (const float*)d_in[4];
    const float* ph_w = (const float*)d_in[5];
    const float* ph_b = (const float*)d_in[6];
    const float* W_w  = (const float*)d_in[7];
    const float* W_b  = (const float*)d_in[8];
    float* out = (float*)d_out;

    const int SMEM = (CI*49 + CI*RGN2 + 512 + 512 + 128) * 4;   // 54400 B
    cudaFuncSetAttribute(k_score, cudaFuncAttributeMaxDynamicSharedMemorySize, SMEM);

    k_zero  <<<(T_*CI*HW + NT-1)/NT, NT>>>();
    k_proj  <<<T_*HW/NT, NT>>>(vid, g_w, g_b, th_w, th_b, ph_w, ph_b);
    k_zcount<<<NQ, PS*PS>>>();
    k_score <<<T_*NQ, NT, SMEM>>>();
    k_final <<<T_*HW/NT, NT>>>(vid, W_w, W_b, out);
}

// round 2
// speedup vs baseline: 1.2616x; 1.2616x over previous
#include <cuda_runtime.h>
#include <math.h>
#include <float.h>

#define T_    4
#define C_    64
#define WW    96
#define HW    9216
#define CI    16
#define PS    7
#define WS    21
#define NQX   24
#define NQ    576
#define NC    441
#define KSEL  100
#define SCALE 10.0f
#define RGN   27
#define RGN2  729
#define NT    256
#define B1P   52            // padded b1 stride per ci (16B-aligned)
#define QST   (RGN*WS)      // 567: Q stride per 'a'

// scratch (no allocations allowed in kernel_launch)
__device__ float g_b1[T_*CI*HW];
__device__ float g_b2[T_*CI*HW];
__device__ float g_b3[T_*CI*HW];
__device__ float g_acc[T_*CI*HW];
__device__ float g_Z[HW];

__device__ __forceinline__ int clipi(int v){ return min(max(v,0),95); }

// ---------------------------------------------------------------- zero
__global__ void k_zero(){
    int i = blockIdx.x*NT + threadIdx.x;
    if (i < T_*CI*HW) g_acc[i] = 0.f;
    if (i < HW)       g_Z[i]   = 0.f;
}

// ---------------------------------------------------------------- Z counts (t-independent)
__global__ void k_zcount(){
    int q  = blockIdx.x;
    int a  = threadIdx.x / PS, b = threadIdx.x % PS;
    int qi = (q / NQX)*4, qj = (q % NQX)*4;
    atomicAdd(&g_Z[min(qi+a,95)*WW + min(qj+b,95)], 1.0f);
}

// ---------------------------------------------------------------- fused 3x conv1x1
__global__ void k_proj(const float* __restrict__ vid,
                       const float* __restrict__ gw, const float* __restrict__ gb,
                       const float* __restrict__ tw, const float* __restrict__ tb,
                       const float* __restrict__ pw, const float* __restrict__ pb){
    __shared__ float sw[3*CI*C_ + 3*CI];
    for (int i=threadIdx.x; i<CI*C_; i+=NT){
        sw[i]          = gw[i];
        sw[CI*C_+i]    = tw[i];
        sw[2*CI*C_+i]  = pw[i];
    }
    if (threadIdx.x < CI){
        sw[3*CI*C_         + threadIdx.x] = gb[threadIdx.x];
        sw[3*CI*C_ +   CI  + threadIdx.x] = tb[threadIdx.x];
        sw[3*CI*C_ + 2*CI  + threadIdx.x] = pb[threadIdx.x];
    }
    __syncthreads();

    int gid = blockIdx.x*NT + threadIdx.x;   // [0, T*HW)
    int t = gid / HW, pix = gid % HW;

    float a1[CI], a2[CI], a3[CI];
    #pragma unroll
    for (int o=0;o<CI;o++){
        a1[o] = sw[3*CI*C_ + o];
        a2[o] = sw[3*CI*C_ + CI + o];
        a3[o] = sw[3*CI*C_ + 2*CI + o];
    }
    const float* vp = vid + (size_t)t*C_*HW + pix;
    for (int c=0;c<C_;c++){
        float v = vp[c*HW];
        #pragma unroll
        for (int o=0;o<CI;o++){
            a1[o] += v*sw[o*C_+c];
            a2[o] += v*sw[CI*C_ + o*C_+c];
            a3[o] += v*sw[2*CI*C_ + o*C_+c];
        }
    }
    float* o1 = g_b1 + (size_t)t*CI*HW + pix;
    float* o2 = g_b2 + (size_t)t*CI*HW + pix;
    float* o3 = g_b3 + (size_t)t*CI*HW + pix;
    #pragma unroll
    for (int o=0;o<CI;o++){ o1[o*HW]=a1[o]; o2[o*HW]=a2[o]; o3[o*HW]=a3[o]; }
}

// ---------------------------------------------------------------- main kernel
// phases: load region+patch+tables -> stage1 (column correlation into Q)
//         -> stage2 (row combine) -> bitonic topk -> softmax
//         -> reload region with b2 -> weighted aggregate -> scatter
__global__ __launch_bounds__(NT) void k_score(){
    extern __shared__ float sm[];
    float* s_b1 = sm;                    // 16*52 = 832
    float* s_rg = s_b1 + CI*B1P;         // 11664
    float* s_Q  = s_rg + CI*RGN2;        // 7*567 = 3969
    float* s_sc = s_Q + 7*QST;           // 512
    int*   s_id = (int*)(s_sc + 512);    // 512
    float* s_w  = (float*)(s_id + 512);  // 128
    int*   s_ro = (int*)(s_w + 128);     // 147
    int*   s_co = s_ro + 147;            // 147
    int*   s_krow = (int*)s_Q;           // alias (Q dead after stage2): 700
    int*   s_kcol = s_krow + 700;        // 700

    int blk = blockIdx.x;
    int t = blk / NQ, q = blk % NQ;
    int qi = (q / NQX)*4, qj = (q % NQX)*4;
    int tid = threadIdx.x;

    int rmin = max(qi-10, 0), cmin = max(qj-10, 0);
    bool colAffine = (qj >= 12 && qj <= 76);

    // ---- clip tables: patch row/col index within region for (d, e)
    if (tid < 147){
        int d_ = tid/7, e_ = tid%7;
        s_ro[tid] = min(clipi(qi + d_ - 10) + e_, 95) - rmin;   // region row index
        s_co[tid] = min(clipi(qj + d_ - 10) + e_, 95) - cmin;   // region col index
    }

    // ---- load b3 region (absolute coords, clipped) + b1 query patch (padded)
    const float* b3t = g_b3 + (size_t)t*CI*HW;
    for (int i=tid; i<CI*RGN2; i+=NT){
        int ci = i / RGN2, rem = i % RGN2;
        int rr = rem / RGN, cc = rem % RGN;
        s_rg[i] = b3t[ci*HW + min(rmin+rr,95)*WW + min(cmin+cc,95)];
    }
    const float* b1t = g_b1 + (size_t)t*CI*HW;
    for (int i=tid; i<CI*49; i+=NT){
        int ci = i/49, rem = i%49, a = rem/7, b = rem%7;
        s_b1[ci*B1P+rem] = b1t[ci*HW + min(qi+a,95)*WW + min(qj+b,95)];
    }
    __syncthreads();

    // ---- stage 1: Q[a][r][dj] = sum_{ci,b} b1[ci,a,b] * R[ci,r,colm(dj,b)]
    if (tid < 189){
        int r = tid/7, cg = tid%7, dj0 = cg*3;
        float acc[7][3];
        #pragma unroll
        for (int a=0;a<7;a++){ acc[a][0]=0.f; acc[a][1]=0.f; acc[a][2]=0.f; }

        if (colAffine){
            for (int ci=0; ci<CI; ci++){
                const float* row = s_rg + ci*RGN2 + r*RGN + dj0;
                float win[9];
                #pragma unroll
                for (int j=0;j<9;j++) win[j] = row[j];
                const float4* bp4 = (const float4*)(s_b1 + ci*B1P);
                #pragma unroll
                for (int v=0; v<12; v++){
                    float4 w4 = bp4[v];
                    #pragma unroll
                    for (int u=0; u<4; u++){
                        int p = 4*v+u;
                        float w = (u==0)?w4.x:(u==1)?w4.y:(u==2)?w4.z:w4.w;
                        int a = p/7, b = p%7;
                        acc[a][0] += w*win[b];
                        acc[a][1] += w*win[b+1];
                        acc[a][2] += w*win[b+2];
                    }
                }
                float w = s_b1[ci*B1P+48];   // p=48 -> a=6,b=6
                acc[6][0] += w*win[6];
                acc[6][1] += w*win[7];
                acc[6][2] += w*win[8];
            }
        } else {
            int cidx[21];
            #pragma unroll
            for (int k=0;k<3;k++)
                #pragma unroll
                for (int b=0;b<7;b++)
                    cidx[k*7+b] = s_co[(dj0+k)*7+b];
            for (int ci=0; ci<CI; ci++){
                const float* row = s_rg + ci*RGN2 + r*RGN;
                float v21[21];
                #pragma unroll
                for (int j=0;j<21;j++) v21[j] = row[cidx[j]];
                const float4* bp4 = (const float4*)(s_b1 + ci*B1P);
                #pragma unroll
                for (int v=0; v<12; v++){
                    float4 w4 = bp4[v];
                    #pragma unroll
                    for (int u=0; u<4; u++){
                        int p = 4*v+u;
                        float w = (u==0)?w4.x:(u==1)?w4.y:(u==2)?w4.z:w4.w;
                        int a = p/7, b = p%7;
                        acc[a][0] += w*v21[b];
                        acc[a][1] += w*v21[7+b];
                        acc[a][2] += w*v21[14+b];
                    }
                }
                float w = s_b1[ci*B1P+48];
                acc[6][0] += w*v21[6];
                acc[6][1] += w*v21[13];
                acc[6][2] += w*v21[20];
            }
        }
        #pragma unroll
        for (int a=0;a<7;a++)
            #pragma unroll
            for (int k=0;k<3;k++)
                s_Q[a*QST + r*WS + dj0 + k] = acc[a][k];
    }
    __syncthreads();

    // ---- stage 2: scores = row-combine of Q via rowmap table
    for (int c=tid; c<512; c+=NT){
        float sc = -FLT_MAX;
        if (c < NC){
            int di = c/WS, dj = c%WS;
            sc = 0.f;
            #pragma unroll
            for (int a=0;a<7;a++)
                sc += s_Q[a*QST + s_ro[di*7+a]*WS + dj];
        }
        s_sc[c] = sc;
        s_id[c] = c;
    }
    __syncthreads();

    // ---- bitonic sort 512 descending
    for (int k=2; k<=512; k<<=1){
        for (int j=k>>1; j>0; j>>=1){
            int lo = tid & (j-1);
            int i0 = ((tid & ~(j-1))<<1) | lo;
            int i1 = i0 | j;
            bool desc = (i0 & k) == 0;
            float k0 = s_sc[i0], k1 = s_sc[i1];
            if ((k0 < k1) == desc){
                s_sc[i0]=k1; s_sc[i1]=k0;
                int tt=s_id[i0]; s_id[i0]=s_id[i1]; s_id[i1]=tt;
            }
            __syncthreads();
        }
    }

    // ---- softmax over top-100
    float maxv = s_sc[0];
    if (tid < KSEL) s_w[tid] = expf((s_sc[tid]-maxv)*SCALE);
    __syncthreads();
    if (tid == 0){
        float s = 0.f;
        for (int k=0;k<KSEL;k++) s += s_w[k];
        s_w[KSEL] = 1.f/s;
    }
    __syncthreads();
    if (tid < KSEL) s_w[tid] *= s_w[KSEL];

    // ---- per-k patch index tables (alias dead Q space) + reload region with b2
    __syncthreads();
    for (int i=tid; i<700; i+=NT){
        int k = i/7, e = i%7, c = s_id[k];
        s_krow[i] = s_ro[(c/WS)*7+e]*RGN;
        s_kcol[i] = s_co[(c%WS)*7+e];
    }
    const float* b2t = g_b2 + (size_t)t*CI*HW;
    for (int i=tid; i<CI*RGN2; i+=NT){
        int ci = i / RGN2, rem = i % RGN2;
        int rr = rem / RGN, cc = rem % RGN;
        s_rg[i] = b2t[ci*HW + min(rmin+rr,95)*WW + min(cmin+cc,95)];
    }
    __syncthreads();

    // ---- zi = sum_k w_k * b2patch(pos_k)
    float accz[4] = {0.f,0.f,0.f,0.f};
    int base[4], aa[4], bb[4];
    #pragma unroll
    for (int r=0;r<4;r++){
        int d = tid + 256*r;
        if (d < CI*49){ int ci=d/49, rem=d%49; base[r]=ci*RGN2; aa[r]=rem/7; bb[r]=rem%7; }
        else { base[r]=0; aa[r]=0; bb[r]=0; }
    }
    for (int k=0;k<KSEL;k++){
        float w = s_w[k];
        const int* kr = s_krow + k*7;
        const int* kc = s_kcol + k*7;
        #pragma unroll
        for (int r=0;r<4;r++){
            int d = tid + 256*r;
            if (d < CI*49)
                accz[r] += w * s_rg[base[r] + kr[aa[r]] + kc[bb[r]]];
        }
    }

    // ---- scatter-add into acc (query-clipped target pixels)
    #pragma unroll
    for (int r=0;r<4;r++){
        int d = tid + 256*r;
        if (d < CI*49){
            int ci = d/49;
            int pix = min(qi+aa[r],95)*WW + min(qj+bb[r],95);
            atomicAdd(&g_acc[(t*CI + ci)*HW + pix], accz[r]);
        }
    }
}

// ---------------------------------------------------------------- y = acc/Z ; out = vid + conv1x1(y)
__global__ void k_final(const float* __restrict__ vid, const float* __restrict__ Ww,
                        const float* __restrict__ Wb, float* __restrict__ out){
    __shared__ float sw[C_*CI + C_];
    for (int i=threadIdx.x; i<C_*CI; i+=NT) sw[i] = Ww[i];
    if (threadIdx.x < C_) sw[C_*CI+threadIdx.x] = Wb[threadIdx.x];
    __syncthreads();

    int gid = blockIdx.x*NT + threadIdx.x;
    int t = gid / HW, pix = gid % HW;

    float inv = 1.f / g_Z[pix];
    float y[CI];
    #pragma unroll
    for (int ci=0;ci<CI;ci++) y[ci] = g_acc[(t*CI+ci)*HW + pix]*inv;

    const float* vp = vid + (size_t)t*C_*HW + pix;
    float*       op = out + (size_t)t*C_*HW + pix;
    for (int co=0;co<C_;co++){
        float s = sw[C_*CI+co];
        #pragma unroll
        for (int ci=0;ci<CI;ci++) s += sw[co*CI+ci]*y[ci];
        op[co*HW] = vp[co*HW] + s;
    }
}

// ---------------------------------------------------------------- launch
extern "C" void kernel_launch(void* const* d_in, const int* in_sizes, int n_in,
                              void* d_out, int out_size){
    const float* vid  = (const float*)d_in[0];
    const float* g_w  = (const float*)d_in[1];
    const float* g_b  = (const float*)d_in[2];
    const float* th_w = (const float*)d_in[3];
    const float* th_b = (const float*)d_in[4];
    const float* ph_w = (const float*)d_in[5];
    const float* ph_b = (const float*)d_in[6];
    const float* W_w  = (const float*)d_in[7];
    const float* W_b  = (const float*)d_in[8];
    float* out = (float*)d_out;

    const int SMEM = (CI*B1P + CI*RGN2 + 7*QST + 512 + 512 + 128 + 147 + 147) * 4; // 71644 B
    cudaFuncSetAttribute(k_score, cudaFuncAttributeMaxDynamicSharedMemorySize, SMEM);

    k_zero  <<<(T_*CI*HW + NT-1)/NT, NT>>>();
    k_proj  <<<T_*HW/NT, NT>>>(vid, g_w, g_b, th_w, th_b, ph_w, ph_b);
    k_zcount<<<NQ, PS*PS>>>();
    k_score <<<T_*NQ, NT, SMEM>>>();
    k_final <<<T_*HW/NT, NT>>>(vid, W_w, W_b, out);
}

// round 3
// speedup vs baseline: 1.4141x; 1.1209x over previous
#include <cuda_runtime.h>
#include <math.h>
#include <float.h>

#define T_    4
#define C_    64
#define WW    96
#define HW    9216
#define CI    16
#define PS    7
#define WS    21
#define NQX   24
#define NQ    576
#define NC    441
#define KSEL  100
#define SCALE 10.0f
#define RGN   27
#define RGN2  729
#define NT    256
#define B1P   52            // padded b1 stride per ci (16B aligned)
#define QST   (RGN*WS)      // 567

// smem layout (floats)
#define SM_B1   0            // 832
#define SM_RG   832          // 11664
#define SM_Q    12496        // 3970 (3969 used, padded for u64 alignment)
#define SM_SRT  16466        // u64[512] -> 1024 floats
#define SM_W    17490        // 104
#define SM_CID  17594        // 100
#define SM_RO   17694        // 147
#define SM_CO   17841        // 147
#define SM_GOFF 17988        // 729
#define SM_TOT  18717        // 74868 bytes

// scratch
__device__ float g_b1[T_*CI*HW];
__device__ float g_b2[T_*CI*HW];
__device__ float g_b3[T_*CI*HW];
__device__ float g_acc[T_*CI*HW];
__device__ float g_Z[HW];

__device__ __forceinline__ int clipi(int v){ return min(max(v,0),95); }
__device__ __forceinline__ unsigned ordf(float f){
    unsigned b = __float_as_uint(f);
    return (b & 0x80000000u) ? ~b : (b | 0x80000000u);
}
__device__ __forceinline__ float iordf(unsigned u){
    unsigned b = (u & 0x80000000u) ? (u & 0x7FFFFFFFu) : ~u;
    return __uint_as_float(b);
}

// ---------------------------------------------------------------- zero
__global__ void k_zero(){
    int i = blockIdx.x*NT + threadIdx.x;
    if (i < T_*CI*HW) g_acc[i] = 0.f;
    if (i < HW)       g_Z[i]   = 0.f;
}

// ---------------------------------------------------------------- Z counts
__global__ void k_zcount(){
    int q  = blockIdx.x;
    int a  = threadIdx.x / PS, b = threadIdx.x % PS;
    int qi = (q / NQX)*4, qj = (q % NQX)*4;
    atomicAdd(&g_Z[min(qi+a,95)*WW + min(qj+b,95)], 1.0f);
}

// ---------------------------------------------------------------- fused 3x conv1x1
__global__ void k_proj(const float* __restrict__ vid,
                       const float* __restrict__ gw, const float* __restrict__ gb,
                       const float* __restrict__ tw, const float* __restrict__ tb,
                       const float* __restrict__ pw, const float* __restrict__ pb){
    __shared__ float sw[3*CI*C_ + 3*CI];
    for (int i=threadIdx.x; i<CI*C_; i+=NT){
        sw[i]          = gw[i];
        sw[CI*C_+i]    = tw[i];
        sw[2*CI*C_+i]  = pw[i];
    }
    if (threadIdx.x < CI){
        sw[3*CI*C_         + threadIdx.x] = gb[threadIdx.x];
        sw[3*CI*C_ +   CI  + threadIdx.x] = tb[threadIdx.x];
        sw[3*CI*C_ + 2*CI  + threadIdx.x] = pb[threadIdx.x];
    }
    __syncthreads();

    int gid = blockIdx.x*NT + threadIdx.x;
    int t = gid / HW, pix = gid % HW;

    float a1[CI], a2[CI], a3[CI];
    #pragma unroll
    for (int o=0;o<CI;o++){
        a1[o] = sw[3*CI*C_ + o];
        a2[o] = sw[3*CI*C_ + CI + o];
        a3[o] = sw[3*CI*C_ + 2*CI + o];
    }
    const float* vp = vid + (size_t)t*C_*HW + pix;
    for (int c=0;c<C_;c++){
        float v = vp[c*HW];
        #pragma unroll
        for (int o=0;o<CI;o++){
            a1[o] += v*sw[o*C_+c];
            a2[o] += v*sw[CI*C_ + o*C_+c];
            a3[o] += v*sw[2*CI*C_ + o*C_+c];
        }
    }
    float* o1 = g_b1 + (size_t)t*CI*HW + pix;
    float* o2 = g_b2 + (size_t)t*CI*HW + pix;
    float* o3 = g_b3 + (size_t)t*CI*HW + pix;
    #pragma unroll
    for (int o=0;o<CI;o++){ o1[o*HW]=a1[o]; o2[o*HW]=a2[o]; o3[o*HW]=a3[o]; }
}

// ---------------------------------------------------------------- main kernel
__global__ __launch_bounds__(NT) void k_score(){
    extern __shared__ float sm[];
    float* s_b1 = sm + SM_B1;
    float* s_rg = sm + SM_RG;
    float* s_Q  = sm + SM_Q;
    unsigned long long* s_srt = (unsigned long long*)(sm + SM_SRT);
    float* s_w   = sm + SM_W;
    int*   s_cid = (int*)(sm + SM_CID);
    int*   s_ro  = (int*)(sm + SM_RO);
    int*   s_co  = (int*)(sm + SM_CO);
    int*   s_goff= (int*)(sm + SM_GOFF);
    int*   s_off = (int*)s_Q;    // alias: Q + srt dead after softmax (4994 >= 4900)

    int blk = blockIdx.x;
    int t = blk / NQ, q = blk % NQ;
    int qi = (q / NQX)*4, qj = (q % NQX)*4;
    int tid = threadIdx.x;

    int rmin = max(qi-10, 0), cmin = max(qj-10, 0);
    bool colAffine = (qj >= 12 && qj <= 76);

    // ---- tables: clip row/col maps + gmem offset table
    if (tid < 147){
        int d_ = tid/7, e_ = tid%7;
        s_ro[tid] = min(clipi(qi + d_ - 10) + e_, 95) - rmin;
        s_co[tid] = min(clipi(qj + d_ - 10) + e_, 95) - cmin;
    }
    for (int i=tid; i<RGN2; i+=NT){
        int rr = i/RGN, cc = i - rr*RGN;
        s_goff[i] = min(rmin+rr,95)*WW + min(cmin+cc,95);
    }
    const float* b1t = g_b1 + (size_t)t*CI*HW;
    for (int i=tid; i<CI*49; i+=NT){
        int ci = i/49, rem = i%49, a = rem/7, b = rem%7;
        s_b1[ci*B1P+rem] = b1t[ci*HW + min(qi+a,95)*WW + min(qj+b,95)];
    }
    __syncthreads();

    // ---- load b3 region through goff (no div/mod)
    {
        const float* b3t = g_b3 + (size_t)t*CI*HW;
        #pragma unroll
        for (int ci=0; ci<CI; ci++){
            const float* src = b3t + ci*HW;
            float* dst = s_rg + ci*RGN2;
            for (int i=tid; i<RGN2; i+=NT) dst[i] = src[s_goff[i]];
        }
    }
    __syncthreads();

    // ---- stage 1: Q[a][r][dj] = sum_{ci,b} b1[ci,a,b] * R[ci,r,colm(dj,b)]
    if (tid < 189){
        int r = tid/7, cg = tid%7, dj0 = cg*3;
        float acc[7][3];
        #pragma unroll
        for (int a=0;a<7;a++){ acc[a][0]=0.f; acc[a][1]=0.f; acc[a][2]=0.f; }

        if (colAffine){
            for (int ci=0; ci<CI; ci++){
                const float* row = s_rg + ci*RGN2 + r*RGN + dj0;
                float win[9];
                #pragma unroll
                for (int j=0;j<9;j++) win[j] = row[j];
                const float4* bp4 = (const float4*)(s_b1 + ci*B1P);
                #pragma unroll
                for (int v=0; v<12; v++){
                    float4 w4 = bp4[v];
                    #pragma unroll
                    for (int u=0; u<4; u++){
                        int p = 4*v+u;
                        float w = (u==0)?w4.x:(u==1)?w4.y:(u==2)?w4.z:w4.w;
                        int a = p/7, b = p%7;
                        acc[a][0] += w*win[b];
                        acc[a][1] += w*win[b+1];
                        acc[a][2] += w*win[b+2];
                    }
                }
                float w = s_b1[ci*B1P+48];
                acc[6][0] += w*win[6];
                acc[6][1] += w*win[7];
                acc[6][2] += w*win[8];
            }
        } else {
            int cidx[21];
            #pragma unroll
            for (int k=0;k<3;k++)
                #pragma unroll
                for (int b=0;b<7;b++)
                    cidx[k*7+b] = s_co[(dj0+k)*7+b];
            for (int ci=0; ci<CI; ci++){
                const float* row = s_rg + ci*RGN2 + r*RGN;
                float v21[21];
                #pragma unroll
                for (int j=0;j<21;j++) v21[j] = row[cidx[j]];
                const float4* bp4 = (const float4*)(s_b1 + ci*B1P);
                #pragma unroll
                for (int v=0; v<12; v++){
                    float4 w4 = bp4[v];
                    #pragma unroll
                    for (int u=0; u<4; u++){
                        int p = 4*v+u;
                        float w = (u==0)?w4.x:(u==1)?w4.y:(u==2)?w4.z:w4.w;
                        int a = p/7, b = p%7;
                        acc[a][0] += w*v21[b];
                        acc[a][1] += w*v21[7+b];
                        acc[a][2] += w*v21[14+b];
                    }
                }
                float w = s_b1[ci*B1P+48];
                acc[6][0] += w*v21[6];
                acc[6][1] += w*v21[13];
                acc[6][2] += w*v21[20];
            }
        }
        #pragma unroll
        for (int a=0;a<7;a++)
            #pragma unroll
            for (int k=0;k<3;k++)
                s_Q[a*QST + r*WS + dj0 + k] = acc[a][k];
    }
    __syncthreads();

    // ---- stage 2: scores -> packed sort keys
    for (int c=tid; c<512; c+=NT){
        unsigned long long key = 0ull;
        if (c < NC){
            int di = c/WS, dj = c%WS;
            float sc = 0.f;
            #pragma unroll
            for (int a=0;a<7;a++)
                sc += s_Q[a*QST + s_ro[di*7+a]*WS + dj];
            key = ((unsigned long long)ordf(sc) << 32) | (unsigned)c;
        }
        s_srt[c] = key;
    }

    // ---- bitonic sort 512 u64 descending
    for (int k=2; k<=512; k<<=1){
        for (int j=k>>1; j>0; j>>=1){
            __syncthreads();
            int lo = tid & (j-1);
            int i0 = ((tid & ~(j-1))<<1) | lo;
            int i1 = i0 | j;
            bool desc = (i0 & k) == 0;
            unsigned long long k0 = s_srt[i0], k1 = s_srt[i1];
            if ((k0 < k1) == desc){ s_srt[i0]=k1; s_srt[i1]=k0; }
        }
    }
    __syncthreads();

    // ---- softmax over top-100 (parallel)
    {
        float maxs = iordf((unsigned)(s_srt[0] >> 32));
        if (tid < KSEL){
            unsigned long long key = s_srt[tid];
            float sc = iordf((unsigned)(key >> 32));
            s_w[tid]   = expf((sc - maxs)*SCALE);
            s_cid[tid] = (int)(key & 0x1FFu);
        }
        __syncthreads();
        if (tid < 32){
            float s = 0.f;
            for (int k=tid; k<KSEL; k+=32) s += s_w[k];
            #pragma unroll
            for (int o=16;o;o>>=1) s += __shfl_xor_sync(0xffffffffu, s, o);
            if (tid == 0) s_w[KSEL] = 1.f/s;
        }
        __syncthreads();
        if (tid < KSEL) s_w[tid] *= s_w[KSEL];
    }

    // ---- build combined offset table s_off[k*49+p] (aliases dead Q/srt)
    for (int i=tid; i<KSEL*49; i+=NT){
        int k = i/49, p = i - k*49;
        int c = s_cid[k];
        int pa = p/7, pb = p - pa*7;
        s_off[i] = s_ro[(c/WS)*7 + pa]*RGN + s_co[(c%WS)*7 + pb];
    }

    // ---- reload region with b2 through goff
    {
        const float* b2t = g_b2 + (size_t)t*CI*HW;
        #pragma unroll
        for (int ci=0; ci<CI; ci++){
            const float* src = b2t + ci*HW;
            float* dst = s_rg + ci*RGN2;
            for (int i=tid; i<RGN2; i+=NT) dst[i] = src[s_goff[i]];
        }
    }
    __syncthreads();

    // ---- aggregation: 196 threads, each owns patch pos p across 4 ci planes
    if (tid < 196){
        int p   = tid % 49;
        int cig = tid / 49;            // 0..3 -> ci = cig*4 + r
        const float* r0 = s_rg + (cig*4+0)*RGN2;
        const float* r1 = s_rg + (cig*4+1)*RGN2;
        const float* r2 = s_rg + (cig*4+2)*RGN2;
        const float* r3 = s_rg + (cig*4+3)*RGN2;
        float a0=0.f, a1=0.f, a2=0.f, a3=0.f;
        const int* offp = s_off + p;
        #pragma unroll 2
        for (int k=0; k<KSEL; k++){
            float w  = s_w[k];
            int  off = offp[k*49];
            a0 += w * r0[off];
            a1 += w * r1[off];
            a2 += w * r2[off];
            a3 += w * r3[off];
        }
        int pa = p/7, pb = p - pa*7;
        int pix = min(qi+pa,95)*WW + min(qj+pb,95);
        float* accb = g_acc + (size_t)(t*CI + cig*4)*HW + pix;
        atomicAdd(accb,        a0);
        atomicAdd(accb +   HW, a1);
        atomicAdd(accb + 2*HW, a2);
        atomicAdd(accb + 3*HW, a3);
    }
}

// ---------------------------------------------------------------- y = acc/Z ; out = vid + conv1x1(y)
__global__ void k_final(const float* __restrict__ vid, const float* __restrict__ Ww,
                        const float* __restrict__ Wb, float* __restrict__ out){
    __shared__ float sw[C_*CI + C_];
    for (int i=threadIdx.x; i<C_*CI; i+=NT) sw[i] = Ww[i];
    if (threadIdx.x < C_) sw[C_*CI+threadIdx.x] = Wb[threadIdx.x];
    __syncthreads();

    int gid = blockIdx.x*NT + threadIdx.x;
    int t = gid / HW, pix = gid % HW;

    float inv = 1.f / g_Z[pix];
    float y[CI];
    #pragma unroll
    for (int ci=0;ci<CI;ci++) y[ci] = g_acc[(t*CI+ci)*HW + pix]*inv;

    const float* vp = vid + (size_t)t*C_*HW + pix;
    float*       op = out + (size_t)t*C_*HW + pix;
    for (int co=0;co<C_;co++){
        float s = sw[C_*CI+co];
        #pragma unroll
        for (int ci=0;ci<CI;ci++) s += sw[co*CI+ci]*y[ci];
        op[co*HW] = vp[co*HW] + s;
    }
}

// ---------------------------------------------------------------- launch
extern "C" void kernel_launch(void* const* d_in, const int* in_sizes, int n_in,
                              void* d_out, int out_size){
    const float* vid  = (const float*)d_in[0];
    const float* g_w  = (const float*)d_in[1];
    const float* g_b  = (const float*)d_in[2];
    const float* th_w = (const float*)d_in[3];
    const float* th_b = (const float*)d_in[4];
    const float* ph_w = (const float*)d_in[5];
    const float* ph_b = (const float*)d_in[6];
    const float* W_w  = (const float*)d_in[7];
    const float* W_b  = (const float*)d_in[8];
    float* out = (float*)d_out;

    const int SMEM = SM_TOT * 4;   // 74868 B
    cudaFuncSetAttribute(k_score, cudaFuncAttributeMaxDynamicSharedMemorySize, SMEM);

    k_zero  <<<(T_*CI*HW + NT-1)/NT, NT>>>();
    k_proj  <<<T_*HW/NT, NT>>>(vid, g_w, g_b, th_w, th_b, ph_w, ph_b);
    k_zcount<<<NQ, PS*PS>>>();
    k_score <<<T_*NQ, NT, SMEM>>>();
    k_final <<<T_*HW/NT, NT>>>(vid, W_w, W_b, out);
}

// round 4
// speedup vs baseline: 1.5697x; 1.1101x over previous
#include <cuda_runtime.h>
#include <math.h>
#include <float.h>

#define T_    4
#define C_    64
#define WW    96
#define HW    9216
#define CI    16
#define PS    7
#define WS    21
#define NQX   24
#define NQ    576
#define NC    441
#define KSEL  100
#define SCALE 10.0f
#define RGN   27
#define RGN2  729
#define NT    256
#define B1P   56            // pair layout: [ci][a][8] (3 pairs + scalar + zero pad)
#define QST   (RGN*WS)      // 567

// smem layout (float offsets)
#define SM_B1   0            // 896
#define SM_RG   896          // 11664
#define SM_Q    12560        // 3970 (Q 3969 + pad)
#define SM_SRT  16530        // u64[512] = 1024 floats
#define SM_W    17556        // 104 (16B aligned)
#define SM_CID  17660        // 100
#define SM_RO   17760        // 147
#define SM_CO   17907        // 147
#define SM_GOFF 18054        // 729
#define SM_TOT  18783        // 75132 bytes

typedef unsigned long long ull;

// scratch
__device__ float g_b1[T_*CI*HW];
__device__ float g_b2[T_*CI*HW];
__device__ float g_b3[T_*CI*HW];
__device__ float g_acc[T_*CI*HW];
__device__ float g_Z[HW];

__device__ __forceinline__ int clipi(int v){ return min(max(v,0),95); }
__device__ __forceinline__ unsigned ordf(float f){
    unsigned b = __float_as_uint(f);
    return (b & 0x80000000u) ? ~b : (b | 0x80000000u);
}
__device__ __forceinline__ float iordf(unsigned u){
    unsigned b = (u & 0x80000000u) ? (u & 0x7FFFFFFFu) : ~u;
    return __uint_as_float(b);
}
__device__ __forceinline__ ull pack2(float lo, float hi){
    ull r; asm("mov.b64 %0, {%1, %2};" : "=l"(r) : "f"(lo), "f"(hi)); return r;
}
__device__ __forceinline__ void fma2(ull &acc, ull a, ull b){
    asm("fma.rn.f32x2 %0, %1, %2, %0;" : "+l"(acc) : "l"(a), "l"(b));
}
__device__ __forceinline__ float sum2(ull v){
    return __uint_as_float((unsigned)v) + __uint_as_float((unsigned)(v>>32));
}

// ---------------------------------------------------------------- zero
__global__ void k_zero(){
    int i = blockIdx.x*NT + threadIdx.x;
    if (i < T_*CI*HW) g_acc[i] = 0.f;
    if (i < HW)       g_Z[i]   = 0.f;
}

// ---------------------------------------------------------------- Z counts
__global__ void k_zcount(){
    int q  = blockIdx.x;
    int a  = threadIdx.x / PS, b = threadIdx.x % PS;
    int qi = (q / NQX)*4, qj = (q % NQX)*4;
    atomicAdd(&g_Z[min(qi+a,95)*WW + min(qj+b,95)], 1.0f);
}

// ---------------------------------------------------------------- fused 3x conv1x1
__global__ void k_proj(const float* __restrict__ vid,
                       const float* __restrict__ gw, const float* __restrict__ gb,
                       const float* __restrict__ tw, const float* __restrict__ tb,
                       const float* __restrict__ pw, const float* __restrict__ pb){
    __shared__ float sw[3*CI*C_ + 3*CI];
    for (int i=threadIdx.x; i<CI*C_; i+=NT){
        sw[i]          = gw[i];
        sw[CI*C_+i]    = tw[i];
        sw[2*CI*C_+i]  = pw[i];
    }
    if (threadIdx.x < CI){
        sw[3*CI*C_         + threadIdx.x] = gb[threadIdx.x];
        sw[3*CI*C_ +   CI  + threadIdx.x] = tb[threadIdx.x];
        sw[3*CI*C_ + 2*CI  + threadIdx.x] = pb[threadIdx.x];
    }
    __syncthreads();

    int gid = blockIdx.x*NT + threadIdx.x;
    int t = gid / HW, pix = gid % HW;

    float a1[CI], a2[CI], a3[CI];
    #pragma unroll
    for (int o=0;o<CI;o++){
        a1[o] = sw[3*CI*C_ + o];
        a2[o] = sw[3*CI*C_ + CI + o];
        a3[o] = sw[3*CI*C_ + 2*CI + o];
    }
    const float* vp = vid + (size_t)t*C_*HW + pix;
    for (int c=0;c<C_;c++){
        float v = vp[c*HW];
        #pragma unroll
        for (int o=0;o<CI;o++){
            a1[o] += v*sw[o*C_+c];
            a2[o] += v*sw[CI*C_ + o*C_+c];
            a3[o] += v*sw[2*CI*C_ + o*C_+c];
        }
    }
    float* o1 = g_b1 + (size_t)t*CI*HW + pix;
    float* o2 = g_b2 + (size_t)t*CI*HW + pix;
    float* o3 = g_b3 + (size_t)t*CI*HW + pix;
    #pragma unroll
    for (int o=0;o<CI;o++){ o1[o*HW]=a1[o]; o2[o*HW]=a2[o]; o3[o*HW]=a3[o]; }
}

// ---------------------------------------------------------------- main kernel
__global__ void __launch_bounds__(NT, 3) k_score(){
    extern __shared__ float sm[];
    float* s_b1 = sm + SM_B1;
    float* s_rg = sm + SM_RG;
    float* s_Q  = sm + SM_Q;
    ull*   s_srt = (ull*)(sm + SM_SRT);
    float* s_w   = sm + SM_W;
    int*   s_cid = (int*)(sm + SM_CID);
    int*   s_ro  = (int*)(sm + SM_RO);
    int*   s_co  = (int*)(sm + SM_CO);
    int*   s_goff= (int*)(sm + SM_GOFF);
    int*   s_offT= (int*)s_Q;    // alias Q+srt (dead after softmax): 4900 <= 4994

    int blk = blockIdx.x;
    int t = blk / NQ, q = blk % NQ;
    int qi = (q / NQX)*4, qj = (q % NQX)*4;
    int tid = threadIdx.x;

    int rmin = max(qi-10, 0), cmin = max(qj-10, 0);
    bool colAffine = (qj >= 12 && qj <= 76);

    // ---- tables
    if (tid < 147){
        int d_ = tid/7, e_ = tid%7;
        s_ro[tid] = min(clipi(qi + d_ - 10) + e_, 95) - rmin;
        s_co[tid] = min(clipi(qj + d_ - 10) + e_, 95) - cmin;
    }
    for (int i=tid; i<RGN2; i+=NT){
        int rr = i/RGN, cc = i - rr*RGN;
        s_goff[i] = min(rmin+rr,95)*WW + min(cmin+cc,95);
    }
    const float* b1t = g_b1 + (size_t)t*CI*HW;
    for (int i=tid; i<CI*49; i+=NT){
        int ci = i/49, rem = i - 49*ci, a = rem/7, b = rem - 7*a;
        s_b1[ci*B1P + a*8 + b] = b1t[ci*HW + min(qi+a,95)*WW + min(qj+b,95)];
    }
    if (tid < CI*7){
        int ci = tid/7, a = tid - 7*ci;
        s_b1[ci*B1P + a*8 + 7] = 0.f;
    }
    __syncthreads();

    // ---- load b3 region: 1 goff LDS feeds 16 independent LDGs
    {
        const float* b3t = g_b3 + (size_t)t*CI*HW;
        for (int i=tid; i<RGN2; i+=NT){
            int go = s_goff[i];
            #pragma unroll
            for (int ci=0;ci<CI;ci++) s_rg[ci*RGN2+i] = b3t[ci*HW+go];
        }
    }
    __syncthreads();

    // ---- stage 1: Q[a][r][dj] via f32x2 even/odd pair accumulation
    if (tid < 189){
        int r = tid/7, dj0 = (tid%7)*3;
        ull acc2[7][3];
        #pragma unroll
        for (int a=0;a<7;a++){ acc2[a][0]=0ull; acc2[a][1]=0ull; acc2[a][2]=0ull; }

        if (colAffine){
            for (int ci=0; ci<CI; ci++){
                const float* row = s_rg + ci*RGN2 + r*RGN + dj0;
                float win[9];
                #pragma unroll
                for (int j=0;j<9;j++) win[j] = row[j];
                ull wp[9];
                #pragma unroll
                for (int b=0;b<8;b++) wp[b] = pack2(win[b], win[b+1]);
                wp[8] = pack2(win[8], 0.f);
                const ull* wq = (const ull*)(s_b1 + ci*B1P);
                #pragma unroll
                for (int a=0;a<7;a++){
                    ull w01 = wq[a*4+0], w23 = wq[a*4+1], w45 = wq[a*4+2], w67 = wq[a*4+3];
                    #pragma unroll
                    for (int k=0;k<3;k++){
                        fma2(acc2[a][k], w01, wp[k]);
                        fma2(acc2[a][k], w23, wp[k+2]);
                        fma2(acc2[a][k], w45, wp[k+4]);
                        fma2(acc2[a][k], w67, wp[k+6]);
                    }
                }
            }
        } else {
            int clim = 95 - cmin;
            int cb[3];
            #pragma unroll
            for (int k=0;k<3;k++) cb[k] = s_co[(dj0+k)*7];
            for (int ci=0; ci<CI; ci++){
                const float* row = s_rg + ci*RGN2 + r*RGN;
                ull vp[3][4];
                #pragma unroll
                for (int k=0;k<3;k++){
                    float w0=row[min(cb[k]+0,clim)], w1=row[min(cb[k]+1,clim)];
                    float w2=row[min(cb[k]+2,clim)], w3=row[min(cb[k]+3,clim)];
                    float w4=row[min(cb[k]+4,clim)], w5=row[min(cb[k]+5,clim)];
                    float w6=row[min(cb[k]+6,clim)], w7=row[min(cb[k]+7,clim)];
                    vp[k][0]=pack2(w0,w1); vp[k][1]=pack2(w2,w3);
                    vp[k][2]=pack2(w4,w5); vp[k][3]=pack2(w6,w7);
                }
                const ull* wq = (const ull*)(s_b1 + ci*B1P);
                #pragma unroll
                for (int a=0;a<7;a++){
                    ull w01 = wq[a*4+0], w23 = wq[a*4+1], w45 = wq[a*4+2], w67 = wq[a*4+3];
                    #pragma unroll
                    for (int k=0;k<3;k++){
                        fma2(acc2[a][k], w01, vp[k][0]);
                        fma2(acc2[a][k], w23, vp[k][1]);
                        fma2(acc2[a][k], w45, vp[k][2]);
                        fma2(acc2[a][k], w67, vp[k][3]);
                    }
                }
            }
        }
        #pragma unroll
        for (int a=0;a<7;a++)
            #pragma unroll
            for (int k=0;k<3;k++)
                s_Q[a*QST + r*WS + dj0 + k] = sum2(acc2[a][k]);
    }
    __syncthreads();

    // ---- prefetch b2 region into registers (hidden behind stage2+sort)
    const float* b2t = g_b2 + (size_t)t*CI*HW;
    int go0 = s_goff[tid];
    int go1 = s_goff[tid+256];
    float vb[32];
    #pragma unroll
    for (int ci=0;ci<CI;ci++){
        vb[ci]    = b2t[ci*HW+go0];
        vb[16+ci] = b2t[ci*HW+go1];
    }

    // ---- stage 2: scores -> packed sort keys
    for (int c=tid; c<512; c+=NT){
        ull key = 0ull;
        if (c < NC){
            int di = c/WS, dj = c - WS*di;
            float sc = 0.f;
            #pragma unroll
            for (int a=0;a<7;a++)
                sc += s_Q[a*QST + s_ro[di*7+a]*WS + dj];
            key = ((ull)ordf(sc) << 32) | (unsigned)c;
        }
        s_srt[c] = key;
    }

    // ---- bitonic sort 512 u64 descending
    for (int k=2; k<=512; k<<=1){
        for (int j=k>>1; j>0; j>>=1){
            __syncthreads();
            int lo = tid & (j-1);
            int i0 = ((tid & ~(j-1))<<1) | lo;
            int i1 = i0 | j;
            bool desc = (i0 & k) == 0;
            ull k0 = s_srt[i0], k1 = s_srt[i1];
            if ((k0 < k1) == desc){ s_srt[i0]=k1; s_srt[i1]=k0; }
        }
    }
    __syncthreads();

    // ---- softmax over top-100
    {
        float maxs = iordf((unsigned)(s_srt[0] >> 32));
        if (tid < KSEL){
            ull key = s_srt[tid];
            float sc = iordf((unsigned)(key >> 32));
            s_w[tid]   = expf((sc - maxs)*SCALE);
            s_cid[tid] = (int)(key & 0x1FFu);
        }
        __syncthreads();
        if (tid < 32){
            float s = 0.f;
            for (int k=tid; k<KSEL; k+=32) s += s_w[k];
            #pragma unroll
            for (int o=16;o;o>>=1) s += __shfl_xor_sync(0xffffffffu, s, o);
            if (tid == 0) s_w[KSEL] = 1.f/s;
        }
        __syncthreads();
        if (tid < KSEL) s_w[tid] *= s_w[KSEL];
    }

    // ---- commit prefetched b2 to smem + tail chunk + transposed offset table
    #pragma unroll
    for (int ci=0;ci<CI;ci++){
        s_rg[ci*RGN2 + tid]       = vb[ci];
        s_rg[ci*RGN2 + tid + 256] = vb[16+ci];
    }
    if (tid + 512 < RGN2){
        int go2 = s_goff[tid+512];
        #pragma unroll
        for (int ci=0;ci<CI;ci++) s_rg[ci*RGN2 + tid + 512] = b2t[ci*HW+go2];
    }
    for (int i=tid; i<KSEL*49; i+=NT){
        int k = i/49, p = i - 49*k;
        int c = s_cid[k];
        int pa = p/7, pb = p - 7*pa;
        s_offT[p*100 + k] = s_ro[(c/WS)*7 + pa]*RGN + s_co[(c%WS)*7 + pb];
    }
    __syncthreads();

    // ---- aggregation: 196 threads, LDS.128 offsets + weights, 16 gathers/step
    if (tid < 196){
        int p   = tid % 49;
        int cig = tid / 49;
        const float* r0 = s_rg + (cig*4+0)*RGN2;
        const float* r1 = s_rg + (cig*4+1)*RGN2;
        const float* r2 = s_rg + (cig*4+2)*RGN2;
        const float* r3 = s_rg + (cig*4+3)*RGN2;
        const int*   offp = s_offT + p*100;
        float a0=0.f, a1=0.f, a2=0.f, a3=0.f;
        #pragma unroll
        for (int k=0; k<KSEL; k+=4){
            int4   o4 = *(const int4*)  (offp + k);
            float4 w4 = *(const float4*)(s_w + k);
            a0 += w4.x*r0[o4.x]; a1 += w4.x*r1[o4.x]; a2 += w4.x*r2[o4.x]; a3 += w4.x*r3[o4.x];
            a0 += w4.y*r0[o4.y]; a1 += w4.y*r1[o4.y]; a2 += w4.y*r2[o4.y]; a3 += w4.y*r3[o4.y];
            a0 += w4.z*r0[o4.z]; a1 += w4.z*r1[o4.z]; a2 += w4.z*r2[o4.z]; a3 += w4.z*r3[o4.z];
            a0 += w4.w*r0[o4.w]; a1 += w4.w*r1[o4.w]; a2 += w4.w*r2[o4.w]; a3 += w4.w*r3[o4.w];
        }
        int pa = p/7, pb = p - 7*pa;
        int pix = min(qi+pa,95)*WW + min(qj+pb,95);
        float* accb = g_acc + (size_t)(t*CI + cig*4)*HW + pix;
        atomicAdd(accb,        a0);
        atomicAdd(accb +   HW, a1);
        atomicAdd(accb + 2*HW, a2);
        atomicAdd(accb + 3*HW, a3);
    }
}

// ---------------------------------------------------------------- y = acc/Z ; out = vid + conv1x1(y)
__global__ void k_final(const float* __restrict__ vid, const float* __restrict__ Ww,
                        const float* __restrict__ Wb, float* __restrict__ out){
    __shared__ float sw[C_*CI + C_];
    for (int i=threadIdx.x; i<C_*CI; i+=NT) sw[i] = Ww[i];
    if (threadIdx.x < C_) sw[C_*CI+threadIdx.x] = Wb[threadIdx.x];
    __syncthreads();

    int gid = blockIdx.x*NT + threadIdx.x;
    int t = gid / HW, pix = gid % HW;

    float inv = 1.f / g_Z[pix];
    float y[CI];
    #pragma unroll
    for (int ci=0;ci<CI;ci++) y[ci] = g_acc[(t*CI+ci)*HW + pix]*inv;

    const float* vp = vid + (size_t)t*C_*HW + pix;
    float*       op = out + (size_t)t*C_*HW + pix;
    for (int co=0;co<C_;co++){
        float s = sw[C_*CI+co];
        #pragma unroll
        for (int ci=0;ci<CI;ci++) s += sw[co*CI+ci]*y[ci];
        op[co*HW] = vp[co*HW] + s;
    }
}

// ---------------------------------------------------------------- launch
extern "C" void kernel_launch(void* const* d_in, const int* in_sizes, int n_in,
                              void* d_out, int out_size){
    const float* vid  = (const float*)d_in[0];
    const float* g_w  = (const float*)d_in[1];
    const float* g_b  = (const float*)d_in[2];
    const float* th_w = (const float*)d_in[3];
    const float* th_b = (const float*)d_in[4];
    const float* ph_w = (const float*)d_in[5];
    const float* ph_b = (const float*)d_in[6];
    const float* W_w  = (const float*)d_in[7];
    const float* W_b  = (const float*)d_in[8];
    float* out = (float*)d_out;

    const int SMEM = SM_TOT * 4;   // 75132 B
    cudaFuncSetAttribute(k_score, cudaFuncAttributeMaxDynamicSharedMemorySize, SMEM);

    k_zero  <<<(T_*CI*HW + NT-1)/NT, NT>>>();
    k_proj  <<<T_*HW/NT, NT>>>(vid, g_w, g_b, th_w, th_b, ph_w, ph_b);
    k_zcount<<<NQ, PS*PS>>>();
    k_score <<<T_*NQ, NT, SMEM>>>();
    k_final <<<T_*HW/NT, NT>>>(vid, W_w, W_b, out);
}